// round 5
// baseline (speedup 1.0000x reference)
#include <cuda_runtime.h>
#include <cuda_bf16.h>

#define NN 8192

// Delta-encoded union-find parent: parent(x) = x + d_pdelta[x]; root iff 0.
// Zero-initialized at module load; hc_finish re-zeroes after every run so no
// init kernel is needed and every replay is deterministic.
__device__ int d_pdelta[NN];
__device__ unsigned int d_ucount;   // strictly-upper positives
__device__ unsigned int d_dcount;   // diagonal positives

// Lock-free union-find on the delta encoding: path halving + CAS hooking
// toward the smaller root.
__device__ __noinline__ void uf_union(int a, int b) {
    while (true) {
        while (true) {                       // find(a)
            int d = d_pdelta[a];
            if (d == 0) break;
            int p = a + d;
            int dp = d_pdelta[p];
            if (dp == 0) { a = p; break; }
            d_pdelta[a] = (p + dp) - a;      // halve: point a at grandparent
            a = p + dp;
        }
        while (true) {                       // find(b)
            int d = d_pdelta[b];
            if (d == 0) break;
            int p = b + d;
            int dp = d_pdelta[p];
            if (dp == 0) { b = p; break; }
            d_pdelta[b] = (p + dp) - b;
            b = p + dp;
        }
        if (a == b) return;
        int lo = min(a, b);
        int hi = max(a, b);
        int old = atomicCAS(&d_pdelta[hi], 0, lo - hi);
        if (old == 0) return;
        a = lo;
        b = hi + old;                        // hi got hooked meanwhile
    }
}

// Cold path: union positives of one quad (cols strictly > row here).
__device__ __noinline__ void union_quad(int row, int col0, float4 v) {
    if (v.x > 0.0f) uf_union(row, col0 + 0);
    if (v.y > 0.0f) uf_union(row, col0 + 1);
    if (v.z > 0.0f) uf_union(row, col0 + 2);
    if (v.w > 0.0f) uf_union(row, col0 + 3);
}

// Upper-triangle scan, pair-stride. Block handles row pairs (p, NN-1-p),
// p += gridDim.x: NN+1 elements per pair -> balanced, ~3.5 pairs/block at
// grid=1184 so the batched inner loop runs long enough to pipeline.
// Exactness: adj bitwise symmetric -> full positives = 2U + D; the
// reference's sum//2 = U + D//2 exactly.
__global__ void __launch_bounds__(256) hc_scan_upper(const float* __restrict__ adj) {
    const int t = threadIdx.x;
    unsigned int cnt = 0;

    for (int pair = blockIdx.x; pair < NN / 2; pair += gridDim.x) {
        #pragma unroll
        for (int half = 0; half < 2; half++) {
            const int row = half ? (NN - 1 - pair) : pair;
            const float4* __restrict__ rowp =
                (const float4*)(adj + (size_t)row * NN);
            const int start4 = row >> 2;     // quad containing the diagonal

            if (t == 0) {
                // diagonal quad: cols may be <, ==, or > row
                float4 v = rowp[start4];
                int col0 = start4 << 2;
                float e[4] = {v.x, v.y, v.z, v.w};
                unsigned dd = 0;
                #pragma unroll
                for (int j = 0; j < 4; j++) {
                    int col = col0 + j;
                    if (e[j] > 0.0f) {
                        if (col == row) dd++;
                        else if (col > row) { cnt++; uf_union(row, col); }
                    }
                }
                if (dd) atomicAdd(&d_dcount, dd);
            }

            const int lim = NN / 4;
            for (int i0 = start4 + 1 + t; i0 < lim; i0 += 1024) {
                const float4 NEG = make_float4(-1.f, -1.f, -1.f, -1.f);
                // batch 4 independent loads before any consumption
                float4 v0 = rowp[i0];
                float4 v1 = NEG, v2 = NEG, v3 = NEG;
                if (i0 + 256 < lim) v1 = rowp[i0 + 256];
                if (i0 + 512 < lim) v2 = rowp[i0 + 512];
                if (i0 + 768 < lim) v3 = rowp[i0 + 768];

                cnt += (unsigned)(v0.x > 0.f) + (unsigned)(v0.y > 0.f)
                     + (unsigned)(v0.z > 0.f) + (unsigned)(v0.w > 0.f);
                cnt += (unsigned)(v1.x > 0.f) + (unsigned)(v1.y > 0.f)
                     + (unsigned)(v1.z > 0.f) + (unsigned)(v1.w > 0.f);
                cnt += (unsigned)(v2.x > 0.f) + (unsigned)(v2.y > 0.f)
                     + (unsigned)(v2.z > 0.f) + (unsigned)(v2.w > 0.f);
                cnt += (unsigned)(v3.x > 0.f) + (unsigned)(v3.y > 0.f)
                     + (unsigned)(v3.z > 0.f) + (unsigned)(v3.w > 0.f);

                float m0 = fmaxf(fmaxf(v0.x, v0.y), fmaxf(v0.z, v0.w));
                float m1 = fmaxf(fmaxf(v1.x, v1.y), fmaxf(v1.z, v1.w));
                float m2 = fmaxf(fmaxf(v2.x, v2.y), fmaxf(v2.z, v2.w));
                float m3 = fmaxf(fmaxf(v3.x, v3.y), fmaxf(v3.z, v3.w));
                if (fmaxf(fmaxf(m0, m1), fmaxf(m2, m3)) > 0.f) {
                    if (m0 > 0.f) union_quad(row, (i0      ) << 2, v0);
                    if (m1 > 0.f) union_quad(row, (i0 + 256) << 2, v1);
                    if (m2 > 0.f) union_quad(row, (i0 + 512) << 2, v2);
                    if (m3 > 0.f) union_quad(row, (i0 + 768) << 2, v3);
                }
            }
        }
    }

    // warp reduce, then block reduce -> 1 atomic per block
    for (int s = 16; s > 0; s >>= 1)
        cnt += __shfl_down_sync(0xFFFFFFFFu, cnt, s);
    __shared__ unsigned int shu[8];
    int lane = t & 31, w = t >> 5;
    if (lane == 0) shu[w] = cnt;
    __syncthreads();
    if (t == 0) {
        unsigned int su = 0;
        #pragma unroll
        for (int i = 0; i < 8; i++) su += shu[i];
        atomicAdd(&d_ucount, su);
    }
}

// Count roots (zero deltas) with int4 loads, compute the loss, then reset
// all device state to zero for the next replay.
__global__ void __launch_bounds__(1024) hc_finish_kernel(float* __restrict__ out) {
    __shared__ int sh[1024];
    const int t = threadIdx.x;
    const int4* p4 = (const int4*)d_pdelta;

    int roots = 0;
    #pragma unroll
    for (int k = 0; k < 2; k++) {
        int4 v = p4[t + k * 1024];
        roots += (v.x == 0) + (v.y == 0) + (v.z == 0) + (v.w == 0);
    }
    sh[t] = roots;
    __syncthreads();
    for (int s = 512; s > 0; s >>= 1) {
        if (t < s) sh[t] += sh[t + s];
        __syncthreads();
    }
    if (t == 0) {
        float n_comp  = (float)sh[0];
        unsigned int half_edges = d_ucount + (d_dcount >> 1);  // (2U+D)//2
        float n_edges = (float)half_edges;
        float betti1  = n_edges - (float)NN + n_comp;
        float n_cyc   = fmaxf(0.0f, betti1);
        float comp_l  = (n_comp - 1.0f) * (n_comp - 1.0f);
        out[0] = comp_l + n_cyc * n_cyc;
    }
    __syncthreads();
    // reset state for the next replay
    int4* w4 = (int4*)d_pdelta;
    #pragma unroll
    for (int k = 0; k < 2; k++)
        w4[t + k * 1024] = make_int4(0, 0, 0, 0);
    if (t == 0) { d_ucount = 0u; d_dcount = 0u; }
}

extern "C" void kernel_launch(void* const* d_in, const int* in_sizes, int n_in,
                              void* d_out, int out_size) {
    const float* adj = (const float*)d_in[0];
    float* out = (float*)d_out;

    hc_scan_upper<<<1184, 256>>>(adj);
    hc_finish_kernel<<<1, 1024>>>(out);
}